// round 7
// baseline (speedup 1.0000x reference)
#include <cuda_runtime.h>
#include <cuda_fp16.h>
#include <mma.h>
#include <cstdint>

using namespace nvcuda;

// ======================= problem constants =======================
#define C_DIM 128
#define MAX_K 512
#define BM 128
#define BN 256
#define EPS 1e-8f

// ======================= smem layout (bytes) =======================
#define LDA_RAW 132                 // fp32 A staging row stride (floats)
#define LDH     136                 // fp16 tile row stride (halves), mult of 8
#define SM_A_RAW 0                                  // 128*132*4 = 67584
#define SM_AH    (128 * LDA_RAW * 4)                // 67584; 128*136*2 = 34816
#define SM_B     (SM_AH + 128 * LDH * 2)            // 102400; 256*136*2 = 69632
#define SM_NRM   (SM_B + 256 * LDH * 2)             // 172032; 256*4 = 1024
#define SMEM_TOTAL (SM_NRM + 1024)                  // 173056

// Scratch: normalized prototypes as fp16. 128 KB.
__device__ __half g_protoH[MAX_K * C_DIM];

// ======================= helpers =======================
__device__ __forceinline__ uint32_t s2u(const void* p) {
    uint32_t a;
    asm("{ .reg .u64 t; cvta.to.shared.u64 t, %1; cvt.u32.u64 %0, t; }" : "=r"(a) : "l"(p));
    return a;
}
__device__ __forceinline__ void cp_async16(uint32_t dst, const void* src) {
    asm volatile("cp.async.cg.shared.global [%0], [%1], 16;" :: "r"(dst), "l"(src));
}
#define CP_COMMIT() asm volatile("cp.async.commit_group;" ::: "memory")
#define CP_WAIT0()  asm volatile("cp.async.wait_group 0;"  ::: "memory")

__device__ __forceinline__ uint32_t h2u(__half2 h) {
    uint32_t u;
    asm("mov.b32 %0, %1;" : "=r"(u) : "r"(*reinterpret_cast<uint32_t*>(&h)));
    return u;
}

// ======================= kernel 1: proto normalize -> fp16 =======================
__global__ void proto_norm_kernel(const float* __restrict__ P, int K) {
    int warp = (blockIdx.x * blockDim.x + threadIdx.x) >> 5;
    int lane = threadIdx.x & 31;
    if (warp >= K) return;
    const float4* row = reinterpret_cast<const float4*>(P + (size_t)warp * C_DIM);
    float4 v = row[lane];
    float s = v.x * v.x + v.y * v.y + v.z * v.z + v.w * v.w;
#pragma unroll
    for (int o = 16; o; o >>= 1) s += __shfl_xor_sync(0xFFFFFFFFu, s, o);
    float inv = 1.0f / fmaxf(sqrtf(s), EPS);
    __half2 h0 = __floats2half2_rn(v.x * inv, v.y * inv);
    __half2 h1 = __floats2half2_rn(v.z * inv, v.w * inv);
    reinterpret_cast<__half2*>(g_protoH + (size_t)warp * C_DIM)[lane * 2 + 0] = h0;
    reinterpret_cast<__half2*>(g_protoH + (size_t)warp * C_DIM)[lane * 2 + 1] = h1;
}

// ======================= kernel 2: persistent fused fp16 GEMM =======================
// grid = (K/BN, STRIDE). Each CTA: fixed column tile, loops row tiles rt += STRIDE.
// Per iter: norm+convert A(rt) [fp32->fp16] -> prefetch A(rt+STRIDE) via cp.async
//           -> wmma fp16 MMA -> epilogue -(1-cos)^2 -> store.
__global__ __launch_bounds__(256, 1)
void hsproto_gemm_kernel(const float* __restrict__ E, float* __restrict__ out,
                         int nRowTiles, int Kout) {
    extern __shared__ char smem[];
    const uint32_t sb = s2u(smem);
    float*  A_raw = reinterpret_cast<float*>(smem + SM_A_RAW);
    __half* A_h   = reinterpret_cast<__half*>(smem + SM_AH);
    __half* B_h   = reinterpret_cast<__half*>(smem + SM_B);
    float*  nrm   = reinterpret_cast<float*>(smem + SM_NRM);

    const int tid = threadIdx.x;
    const int colBase = blockIdx.x * BN;
    const int STRIDE = gridDim.y;

    // per-thread A staging mapping: half a row each
    const int r = tid >> 1;          // 0..127
    const int h = tid & 1;           // half: 0 or 1 (64 floats)
    const uint32_t aRawDst = sb + SM_A_RAW + (uint32_t)(r * LDA_RAW + h * 64) * 4;

    // ---- prologue: async-load B tile (fp16, row tid) + first A tile ----
    {
        const __half* gB = g_protoH + (size_t)(colBase + tid) * C_DIM;
        uint32_t bDst = sb + SM_B + (uint32_t)tid * (LDH * 2);
#pragma unroll
        for (int j = 0; j < 16; j++) cp_async16(bDst + j * 16, gB + j * 8);

        const float* gA = E + ((size_t)blockIdx.y * BM + r) * C_DIM + h * 64;
#pragma unroll
        for (int j = 0; j < 16; j++) cp_async16(aRawDst + j * 16, gA + j * 4);
        CP_COMMIT();
        CP_WAIT0();
    }

    const int warpId = tid >> 5;
    const int wm = warpId >> 2;      // 0..1 -> row offset wm*64
    const int wn = warpId & 3;       // 0..3 -> col offset wn*64

    for (int rt = blockIdx.y; rt < nRowTiles; rt += STRIDE) {
        // ---- row norms of A_raw (fp32): each thread sums its 64 floats ----
        float s = 0.0f;
        const float* myRaw = A_raw + r * LDA_RAW + h * 64;
#pragma unroll
        for (int j = 0; j < 16; j++) {
            float4 v = reinterpret_cast<const float4*>(myRaw)[j];
            s += v.x * v.x + v.y * v.y + v.z * v.z + v.w * v.w;
        }
        nrm[tid] = s;
        __syncthreads();                                   // sync1
        float inv = 1.0f / fmaxf(sqrtf(nrm[r * 2] + nrm[r * 2 + 1]), EPS);

        // ---- scale + convert to fp16 into A_h ----
        __half* myH = A_h + r * LDH + h * 64;
#pragma unroll
        for (int j = 0; j < 8; j++) {
            float4 v0 = reinterpret_cast<const float4*>(myRaw)[j * 2 + 0];
            float4 v1 = reinterpret_cast<const float4*>(myRaw)[j * 2 + 1];
            __half2 p0 = __floats2half2_rn(v0.x * inv, v0.y * inv);
            __half2 p1 = __floats2half2_rn(v0.z * inv, v0.w * inv);
            __half2 p2 = __floats2half2_rn(v1.x * inv, v1.y * inv);
            __half2 p3 = __floats2half2_rn(v1.z * inv, v1.w * inv);
            uint4 pk;
            pk.x = h2u(p0); pk.y = h2u(p1);
            pk.z = h2u(p2); pk.w = h2u(p3);
            reinterpret_cast<uint4*>(myH)[j] = pk;
        }
        __syncthreads();                                   // sync2: A_h/B visible, A_raw free

        // ---- prefetch next A tile (overlaps MMA + epilogue) ----
        int nrt = rt + STRIDE;
        if (nrt < nRowTiles) {
            const float* gA = E + ((size_t)nrt * BM + r) * C_DIM + h * 64;
#pragma unroll
            for (int j = 0; j < 16; j++) cp_async16(aRawDst + j * 16, gA + j * 4);
            CP_COMMIT();
        }

        // ---- fp16 tensor-core GEMM: warp tile 64x64, 4x4 m16n16k16 ----
        wmma::fragment<wmma::accumulator, 16, 16, 16, float> acc[4][4];
#pragma unroll
        for (int i = 0; i < 4; i++)
#pragma unroll
            for (int j = 0; j < 4; j++) wmma::fill_fragment(acc[i][j], 0.0f);

#pragma unroll
        for (int kk = 0; kk < C_DIM; kk += 16) {
            wmma::fragment<wmma::matrix_a, 16, 16, 16, __half, wmma::row_major> a[4];
            wmma::fragment<wmma::matrix_b, 16, 16, 16, __half, wmma::col_major> b[4];
#pragma unroll
            for (int i = 0; i < 4; i++)
                wmma::load_matrix_sync(a[i], A_h + (wm * 64 + i * 16) * LDH + kk, LDH);
#pragma unroll
            for (int j = 0; j < 4; j++)
                wmma::load_matrix_sync(b[j], B_h + (wn * 64 + j * 16) * LDH + kk, LDH);
#pragma unroll
            for (int i = 0; i < 4; i++)
#pragma unroll
                for (int j = 0; j < 4; j++)
                    wmma::mma_sync(acc[i][j], a[i], b[j], acc[i][j]);
        }

        // ---- epilogue: -(1-cos)^2 in regs, store straight to GMEM ----
        float* outBase = out + ((size_t)rt * BM) * Kout + colBase;
#pragma unroll
        for (int i = 0; i < 4; i++) {
#pragma unroll
            for (int j = 0; j < 4; j++) {
#pragma unroll
                for (int e = 0; e < acc[i][j].num_elements; e++) {
                    float d = 1.0f - acc[i][j].x[e];
                    acc[i][j].x[e] = -(d * d);
                }
                wmma::store_matrix_sync(outBase + (size_t)(wm * 64 + i * 16) * Kout
                                                + (wn * 64 + j * 16),
                                        acc[i][j], Kout, wmma::mem_row_major);
            }
        }

        CP_WAIT0();   // next A_raw resident before top-of-loop reads
    }
}

// ======================= launcher =======================
extern "C" void kernel_launch(void* const* d_in, const int* in_sizes, int n_in,
                              void* d_out, int out_size) {
    const float* E = (const float*)d_in[0];
    const float* P = (const float*)d_in[1];
    float* out = (float*)d_out;

    const int N = in_sizes[0] / C_DIM;   // 131072
    const int K = in_sizes[1] / C_DIM;   // 512

    proto_norm_kernel<<<(K * 32 + 255) / 256, 256>>>(P, K);

    static int sms = 0;
    if (!sms) {
        cudaDeviceGetAttribute(&sms, cudaDevAttrMultiProcessorCount, 0);
        cudaFuncSetAttribute(hsproto_gemm_kernel,
                             cudaFuncAttributeMaxDynamicSharedMemorySize, SMEM_TOTAL);
    }
    const int nColTiles = K / BN;                 // 2
    int stripe = sms / nColTiles;                 // persistent CTAs per column
    if (stripe < 1) stripe = 1;
    const int nRowTiles = N / BM;                 // 1024
    if (stripe > nRowTiles) stripe = nRowTiles;

    dim3 grid(nColTiles, stripe);
    hsproto_gemm_kernel<<<grid, 256, SMEM_TOTAL>>>(E, out, nRowTiles, K);
}

// round 8
// speedup vs baseline: 1.0109x; 1.0109x over previous
#include <cuda_runtime.h>
#include <cuda_fp16.h>
#include <mma.h>
#include <cstdint>

using namespace nvcuda;

// ======================= problem constants =======================
#define C_DIM 128
#define MAX_K 512
#define BM 128
#define BN 256
#define EPS 1e-8f

// ======================= smem layout (bytes) =======================
#define LDA_RAW 132                 // fp32 A staging row stride (floats)
#define LDH     136                 // fp16 tile row stride (halves)
#define SM_A_RAW 0                                   // 128*132*4 = 67584
#define SM_AH0   (128 * LDA_RAW * 4)                 // 67584 (+34816)
#define SM_AH1   (SM_AH0 + 128 * LDH * 2)            // 102400 (+34816)
#define SM_B     (SM_AH1 + 128 * LDH * 2)            // 137216 (+69632)
#define SMEM_TOTAL (SM_B + 256 * LDH * 2)            // 206848

// Scratch: normalized prototypes as fp16. 128 KB.
__device__ __half g_protoH[MAX_K * C_DIM];

// ======================= helpers =======================
__device__ __forceinline__ uint32_t s2u(const void* p) {
    uint32_t a;
    asm("{ .reg .u64 t; cvta.to.shared.u64 t, %1; cvt.u32.u64 %0, t; }" : "=r"(a) : "l"(p));
    return a;
}
__device__ __forceinline__ void cp_async16(uint32_t dst, const void* src) {
    asm volatile("cp.async.cg.shared.global [%0], [%1], 16;" :: "r"(dst), "l"(src));
}
#define CP_COMMIT() asm volatile("cp.async.commit_group;" ::: "memory")
#define CP_WAIT0()  asm volatile("cp.async.wait_group 0;"  ::: "memory")

__device__ __forceinline__ uint32_t h2u(__half2 h) {
    return *reinterpret_cast<uint32_t*>(&h);
}

// ======================= kernel 1: proto normalize -> fp16 =======================
__global__ void proto_norm_kernel(const float* __restrict__ P, int K) {
    int warp = (blockIdx.x * blockDim.x + threadIdx.x) >> 5;
    int lane = threadIdx.x & 31;
    if (warp >= K) return;
    const float4* row = reinterpret_cast<const float4*>(P + (size_t)warp * C_DIM);
    float4 v = row[lane];
    float s = v.x * v.x + v.y * v.y + v.z * v.z + v.w * v.w;
#pragma unroll
    for (int o = 16; o; o >>= 1) s += __shfl_xor_sync(0xFFFFFFFFu, s, o);
    float inv = 1.0f / fmaxf(sqrtf(s), EPS);
    __half2 h0 = __floats2half2_rn(v.x * inv, v.y * inv);
    __half2 h1 = __floats2half2_rn(v.z * inv, v.w * inv);
    reinterpret_cast<__half2*>(g_protoH + (size_t)warp * C_DIM)[lane * 2 + 0] = h0;
    reinterpret_cast<__half2*>(g_protoH + (size_t)warp * C_DIM)[lane * 2 + 1] = h1;
}

// ======================= kernel 2: persistent pipelined fp16 GEMM =======================
// 256 thr. Per iter: MMA(t) || convert(t+1) in HMMA shadow; epilogue(t); prefetch(t+2).
__global__ __launch_bounds__(256, 1)
void hsproto_gemm_kernel(const float* __restrict__ E, float* __restrict__ out,
                         int nRowTiles, int Kout) {
    extern __shared__ char smem[];
    const uint32_t sb = s2u(smem);
    float*  A_raw = reinterpret_cast<float*>(smem + SM_A_RAW);
    __half* B_h   = reinterpret_cast<__half*>(smem + SM_B);

    const int tid = threadIdx.x;
    const int colBase = blockIdx.x * BN;
    const int STRIDE = gridDim.y;

    const int r = tid >> 1;          // row 0..127
    const int h = tid & 1;           // half 0/1 (64 floats)
    const float* myRaw = A_raw + r * LDA_RAW + h * 64;
    const uint32_t aRawDst = sb + SM_A_RAW + (uint32_t)(r * LDA_RAW + h * 64) * 4;

    // ---- prologue: B tile + first A tile ----
    {
        const __half* gB = g_protoH + (size_t)(colBase + tid) * C_DIM;
        uint32_t bDst = sb + SM_B + (uint32_t)tid * (LDH * 2);
#pragma unroll
        for (int j = 0; j < 16; j++) cp_async16(bDst + j * 16, gB + j * 8);

        const float* gA = E + ((size_t)blockIdx.y * BM + r) * C_DIM + h * 64;
#pragma unroll
        for (int j = 0; j < 16; j++) cp_async16(aRawDst + j * 16, gA + j * 4);
        CP_COMMIT();
        CP_WAIT0();
    }

    // convert(first) -> A_h buffer 0  (norm via shfl with half-partner tid^1)
    {
        float s = 0.0f;
#pragma unroll
        for (int j = 0; j < 16; j++) {
            float4 v = reinterpret_cast<const float4*>(myRaw)[j];
            s += v.x * v.x + v.y * v.y + v.z * v.z + v.w * v.w;
        }
        s += __shfl_xor_sync(0xFFFFFFFFu, s, 1);
        float inv = 1.0f / fmaxf(sqrtf(s), EPS);
        __half* myH = reinterpret_cast<__half*>(smem + SM_AH0) + r * LDH + h * 64;
#pragma unroll
        for (int j = 0; j < 8; j++) {
            float4 v0 = reinterpret_cast<const float4*>(myRaw)[j * 2 + 0];
            float4 v1 = reinterpret_cast<const float4*>(myRaw)[j * 2 + 1];
            uint4 pk;
            pk.x = h2u(__floats2half2_rn(v0.x * inv, v0.y * inv));
            pk.y = h2u(__floats2half2_rn(v0.z * inv, v0.w * inv));
            pk.z = h2u(__floats2half2_rn(v1.x * inv, v1.y * inv));
            pk.w = h2u(__floats2half2_rn(v1.z * inv, v1.w * inv));
            reinterpret_cast<uint4*>(myH)[j] = pk;
        }
    }
    __syncthreads();                       // A_h0 visible; A_raw reads done

    // prefetch A_raw(second)
    if (blockIdx.y + STRIDE < nRowTiles) {
        const float* gA = E + ((size_t)(blockIdx.y + STRIDE) * BM + r) * C_DIM + h * 64;
#pragma unroll
        for (int j = 0; j < 16; j++) cp_async16(aRawDst + j * 16, gA + j * 4);
        CP_COMMIT();
    }

    const int warpId = tid >> 5;
    const int wm = warpId >> 2;      // 0..1 -> row offset wm*64
    const int wn = warpId & 3;       // 0..3 -> col offset wn*64
    int buf = 0;

    for (int rt = blockIdx.y; rt < nRowTiles; rt += STRIDE) {
        const __half* A_h = reinterpret_cast<const __half*>(smem + (buf ? SM_AH1 : SM_AH0));

        // ---- fp16 tensor-core GEMM: warp tile 64x64, 4x4 m16n16k16 ----
        wmma::fragment<wmma::accumulator, 16, 16, 16, float> acc[4][4];
#pragma unroll
        for (int i = 0; i < 4; i++)
#pragma unroll
            for (int j = 0; j < 4; j++) wmma::fill_fragment(acc[i][j], 0.0f);

#pragma unroll
        for (int kk = 0; kk < C_DIM; kk += 16) {
            wmma::fragment<wmma::matrix_a, 16, 16, 16, __half, wmma::row_major> a[4];
            wmma::fragment<wmma::matrix_b, 16, 16, 16, __half, wmma::col_major> b[4];
#pragma unroll
            for (int i = 0; i < 4; i++)
                wmma::load_matrix_sync(a[i], A_h + (wm * 64 + i * 16) * LDH + kk, LDH);
#pragma unroll
            for (int j = 0; j < 4; j++)
                wmma::load_matrix_sync(b[j], B_h + (wn * 64 + j * 16) * LDH + kk, LDH);
#pragma unroll
            for (int i = 0; i < 4; i++)
#pragma unroll
                for (int j = 0; j < 4; j++)
                    wmma::mma_sync(acc[i][j], a[i], b[j], acc[i][j]);
        }

        // ---- convert(t+1) in the HMMA shadow (no dependence on acc) ----
        int nrt = rt + STRIDE;
        if (nrt < nRowTiles) {
            CP_WAIT0();                    // A_raw(t+1) resident
            float s = 0.0f;
#pragma unroll
            for (int j = 0; j < 16; j++) {
                float4 v = reinterpret_cast<const float4*>(myRaw)[j];
                s += v.x * v.x + v.y * v.y + v.z * v.z + v.w * v.w;
            }
            s += __shfl_xor_sync(0xFFFFFFFFu, s, 1);
            float inv = 1.0f / fmaxf(sqrtf(s), EPS);
            __half* myH = reinterpret_cast<__half*>(smem + (buf ? SM_AH0 : SM_AH1))
                          + r * LDH + h * 64;
#pragma unroll
            for (int j = 0; j < 8; j++) {
                float4 v0 = reinterpret_cast<const float4*>(myRaw)[j * 2 + 0];
                float4 v1 = reinterpret_cast<const float4*>(myRaw)[j * 2 + 1];
                uint4 pk;
                pk.x = h2u(__floats2half2_rn(v0.x * inv, v0.y * inv));
                pk.y = h2u(__floats2half2_rn(v0.z * inv, v0.w * inv));
                pk.z = h2u(__floats2half2_rn(v1.x * inv, v1.y * inv));
                pk.w = h2u(__floats2half2_rn(v1.z * inv, v1.w * inv));
                reinterpret_cast<uint4*>(myH)[j] = pk;
            }
        }

        // ---- epilogue(t): -(1-cos)^2, store to GMEM (waits on HMMA scoreboard) ----
        float* outBase = out + ((size_t)rt * BM) * Kout + colBase;
#pragma unroll
        for (int i = 0; i < 4; i++) {
#pragma unroll
            for (int j = 0; j < 4; j++) {
#pragma unroll
                for (int e = 0; e < acc[i][j].num_elements; e++) {
                    float d = 1.0f - acc[i][j].x[e];
                    acc[i][j].x[e] = -(d * d);
                }
                wmma::store_matrix_sync(outBase + (size_t)(wm * 64 + i * 16) * Kout
                                                + (wn * 64 + j * 16),
                                        acc[i][j], Kout, wmma::mem_row_major);
            }
        }

        __syncthreads();                   // next A_h ready; A_raw reads all done

        // ---- prefetch A_raw(t+2): after the bar => read-before-write guaranteed ----
        if (rt + 2 * STRIDE < nRowTiles) {
            const float* gA = E + ((size_t)(rt + 2 * STRIDE) * BM + r) * C_DIM + h * 64;
#pragma unroll
            for (int j = 0; j < 16; j++) cp_async16(aRawDst + j * 16, gA + j * 4);
            CP_COMMIT();
        }
        buf ^= 1;
    }
}

// ======================= launcher =======================
extern "C" void kernel_launch(void* const* d_in, const int* in_sizes, int n_in,
                              void* d_out, int out_size) {
    const float* E = (const float*)d_in[0];
    const float* P = (const float*)d_in[1];
    float* out = (float*)d_out;

    const int N = in_sizes[0] / C_DIM;   // 131072
    const int K = in_sizes[1] / C_DIM;   // 512

    proto_norm_kernel<<<(K * 32 + 255) / 256, 256>>>(P, K);

    static int sms = 0;
    if (!sms) {
        cudaDeviceGetAttribute(&sms, cudaDevAttrMultiProcessorCount, 0);
        cudaFuncSetAttribute(hsproto_gemm_kernel,
                             cudaFuncAttributeMaxDynamicSharedMemorySize, SMEM_TOTAL);
    }
    const int nColTiles = K / BN;                 // 2
    int stripe = sms / nColTiles;                 // persistent CTAs per column
    if (stripe < 1) stripe = 1;
    const int nRowTiles = N / BM;                 // 1024
    if (stripe > nRowTiles) stripe = nRowTiles;

    dim3 grid(nColTiles, stripe);
    hsproto_gemm_kernel<<<grid, 256, SMEM_TOTAL>>>(E, out, nRowTiles, K);
}